// round 14
// baseline (speedup 1.0000x reference)
#include <cuda_runtime.h>
#include <cuda_fp16.h>
#include <math.h>
#include <stdint.h>

// ---------------- problem constants ----------------
#define B_    256
#define T_    100
#define INF   227
#define HID_  1024
#define NG    4096          // 4*HID
#define KP1   1280          // layer1 K: [h(1024) | x(227 pad 256)]
#define KP2   2048
#define SL    (B_*HID_)

#define W1SZ  (NG*KP1)
#define W2SZ  (NG*KP2)
#define WTOT  (W1SZ + 2*W2SZ)
#define A2SZ  (B_*KP2)      // one [h|h] activation panel
#define APAR  (2*A2SZ)      // layer2 + layer3 panels per parity

// gates tiles: CTA 64x128, K-chunk 128, pitch 272B (17x16B -> conflict-free)
#define PITCHG  272
#define TILEA   (64*PITCHG)      // 17408
#define TILEBW  (128*PITCHG)     // 34816
#define GSTAGEB (TILEA+TILEBW)   // 52224
#define NSTAGE  3

// dense tiles: CTA 64x128, K-chunk 64, 3-term (Ah,Al,Bh,Bl), pitch 144B
#define PITCHD  144
#define DTA     (64*PITCHD)      // 9216
#define DTB     (128*PITCHD)     // 18432
#define DSTAGEB (2*DTA+2*DTB)    // 55296
#define SMEM_ALL (NSTAGE*DSTAGEB) // 165888 (> NSTAGE*GSTAGEB)

#define NCTA    148

// ---------------- static device scratch ----------------
__device__ __align__(16) __half g_Wh[WTOT];     // weights fp16, [n][k]
__device__ __align__(16) __half g_A [2*APAR];   // [parity][L2 panel | L3 panel]
__device__ __align__(16) __half g_Ax[(size_t)T_*B_*256]; // per-step x frames
__device__ __align__(16) float g_bias[3*NG];    // bih+bhh, ifgo quads
__device__ __align__(16) __half g_BdH[256*HID_];// Wd fp16 hi, [n][k], rows>=227 zero
__device__ __align__(16) __half g_BdL[256*HID_];// Wd fp16 lo
__device__ __align__(16) float g_c[3*SL];       // cell states fp32
__device__ __align__(16) __half g_histH[(size_t)T_*SL]; // h2 history hi
__device__ __align__(16) __half g_histL[(size_t)T_*SL]; // h2 history lo
__device__ unsigned g_ticket[T_];               // per-step job tickets
__device__ unsigned g_cnt[T_][3][4];            // (step, layer, mtile) done counts
__device__ unsigned g_fbdone[T_];               // per-step feedback done count

// fast transcendentals (MUFU.EX2 path; ~2 ulp, negligible vs fp16 floor)
__device__ __forceinline__ float sigf_(float x)  { return 1.0f / (1.0f + __expf(-x)); }
__device__ __forceinline__ float tanhf_(float x) { return 2.0f / (1.0f + __expf(-2.0f * x)) - 1.0f; }

// ---------------- PTX helpers (plain sm_80+ features only) ----------------
__device__ __forceinline__ uint32_t smem_u32(const void* p) {
    uint32_t a;
    asm("{ .reg .u64 t; cvta.to.shared.u64 t, %1; cvt.u32.u64 %0, t; }" : "=r"(a) : "l"(p));
    return a;
}
__device__ __forceinline__ void cp16(uint32_t d, const void* g) {
    asm volatile("cp.async.cg.shared.global [%0], [%1], 16;" :: "r"(d), "l"(g) : "memory");
}
__device__ __forceinline__ void cp_commit() {
    asm volatile("cp.async.commit_group;" ::: "memory");
}
__device__ __forceinline__ void ldm_x4(uint32_t* r, uint32_t a) {
    asm volatile("ldmatrix.sync.aligned.m8n8.x4.shared.b16 {%0,%1,%2,%3}, [%4];"
                 : "=r"(r[0]), "=r"(r[1]), "=r"(r[2]), "=r"(r[3]) : "r"(a));
}
__device__ __forceinline__ void mma16816(float* c, const uint32_t* a, uint32_t b0, uint32_t b1) {
    asm volatile("mma.sync.aligned.m16n8k16.row.col.f32.f16.f16.f32 "
                 "{%0,%1,%2,%3}, {%4,%5,%6,%7}, {%8,%9}, {%0,%1,%2,%3};"
                 : "+f"(c[0]), "+f"(c[1]), "+f"(c[2]), "+f"(c[3])
                 : "r"(a[0]), "r"(a[1]), "r"(a[2]), "r"(a[3]), "r"(b0), "r"(b1));
}
// L2-coherent spin (L1 not flushed inside a persistent launch)
__device__ __forceinline__ void spin_ge(const unsigned* p, unsigned tgt) {
    for (;;) {
        unsigned v;
        asm volatile("ld.global.cg.u32 %0, [%1];" : "=r"(v) : "l"(p));
        if (v >= tgt) return;
        __nanosleep(64);
    }
}

// ---------------- zero mutable state each replay ----------------
__global__ void k_zero() {
    const size_t CW = (size_t)3 * SL;
    const size_t AW = (size_t)APAR;
    const size_t N  = CW + AW + 14 * T_;
    for (size_t i = (size_t)blockIdx.x * blockDim.x + threadIdx.x; i < N;
         i += (size_t)gridDim.x * blockDim.x) {
        if (i < CW)                      g_c[i] = 0.0f;
        else if (i < CW + AW)            ((uint32_t*)g_A)[i - CW] = 0u;
        else if (i < CW + AW + T_)       g_ticket[i - CW - AW] = 0u;
        else if (i < CW + AW + 13 * T_)  ((unsigned*)g_cnt)[i - CW - AW - T_] = 0u;
        else                             g_fbdone[i - CW - AW - 13 * T_] = 0u;
    }
}

// ---------------- weight reorder + fp16 ----------------
__global__ void k_setup(const float* __restrict__ Wih1, const float* __restrict__ Whh1,
                        const float* __restrict__ Wih2, const float* __restrict__ Whh2,
                        const float* __restrict__ Wih3, const float* __restrict__ Whh3,
                        const float* __restrict__ bih1, const float* __restrict__ bhh1,
                        const float* __restrict__ bih2, const float* __restrict__ bhh2,
                        const float* __restrict__ bih3, const float* __restrict__ bhh3) {
    const long TOT = (long)WTOT + 3L * NG;
    for (long idx = (long)blockIdx.x * blockDim.x + threadIdx.x; idx < TOT;
         idx += (long)gridDim.x * blockDim.x) {
        long r = idx;
        if (r < (long)WTOT) {
            int z, n, k;
            if (r < W1SZ)              { z = 0; n = (int)(r / KP1); k = (int)(r % KP1); }
            else if (r < W1SZ + W2SZ)  { long q = r - W1SZ; z = 1; n = (int)(q / KP2); k = (int)(q % KP2); }
            else                       { long q = r - W1SZ - W2SZ; z = 2; n = (int)(q / KP2); k = (int)(q % KP2); }
            int R = (n & 3) * HID_ + (n >> 2);
            float w = 0.0f;
            if (z == 0) {
                if (k < HID_)           w = Whh1[(size_t)R * HID_ + k];
                else if (k < HID_+INF)  w = Wih1[(size_t)R * INF + (k - HID_)];
            } else if (z == 1) {
                w = (k < HID_) ? Wih2[(size_t)R * HID_ + k] : Whh2[(size_t)R * HID_ + (k - HID_)];
            } else {
                w = (k < HID_) ? Wih3[(size_t)R * HID_ + k] : Whh3[(size_t)R * HID_ + (k - HID_)];
            }
            g_Wh[r] = __float2half_rn(w);
            continue;
        }
        r -= WTOT;
        {
            int L = (int)(r / NG), n = (int)(r % NG);
            int R = (n & 3) * HID_ + (n >> 2);
            float v = (L == 0) ? bih1[R] + bhh1[R]
                    : (L == 1) ? bih2[R] + bhh2[R]
                               : bih3[R] + bhh3[R];
            g_bias[r] = v;
        }
    }
}

__global__ void k_setup_bd(const float* __restrict__ Wd) {
    int i = blockIdx.x * blockDim.x + threadIdx.x;
    if (i >= 256 * HID_) return;
    int n = i / HID_, k = i % HID_;
    float w = (n < INF) ? Wd[(size_t)n * HID_ + k] : 0.0f;
    __half hi = __float2half_rn(w);
    g_BdH[i] = hi;
    g_BdL[i] = __float2half_rn(w - __half2float(hi));
}

__global__ void stage_x(const float* __restrict__ rs) {
    long i = (long)blockIdx.x * blockDim.x + threadIdx.x;
    if (i >= (long)T_ * B_ * 256) return;
    int n = (int)(i & 255);
    int b = (int)((i >> 8) & 255);
    int t = (int)(i >> 16);
    float v = 0.0f;
    if (n < INF && (t % 10) < 5)
        v = rs[(size_t)b * (T_ * INF) + (size_t)t * INF + n];
    g_Ax[i] = __float2half_rn(v);
}

// ---------------- single persistent kernel: 100 steps + fb + dense ----------
// Per-step tickets: [0,256) z1/z2 | [256,384) z0 | [384,384+nfb) fb |
//                   [.., +8) dense rows t*256+mt*64 (dep: cnt2[t][mt]=32).
__global__ void __launch_bounds__(256, 1) gates_kernel(const float* __restrict__ bd,
                                                       float* __restrict__ out) {
    extern __shared__ char dynsmem[];
    __shared__ int s_job;
    const int tid = threadIdx.x;
    const int warp = tid >> 5, lane = tid & 31;
    const int warpm = warp >> 2, warpn = warp & 3;
    const uint32_t sbase = smem_u32(dynsmem);

    int t = 0;
    for (;;) {
        if (tid == 0) s_job = (int)atomicAdd(&g_ticket[t], 1u);
        __syncthreads();
        const int jid = s_job;
        __syncthreads();
        const int hasfb = (t < T_ - 1) && (((t + 1) % 10) >= 5);
        const int nfb = hasfb ? 8 : 0;
        const int njobs = 384 + nfb + 8;
        if (jid >= njobs) {
            if (++t >= T_) return;
            continue;
        }
        const int p = t & 1, pn = p ^ 1;
        const __half* __restrict__ Apar = g_A + (size_t)p * APAR;

        // ================= DENSE JOB =================
        if (jid >= 384 + nfb) {
            int idx = jid - 384 - nfb;
            const int mt = idx & 3, nt = (idx >> 2) & 1;
            const int rowg0 = t * 256 + mt * 64;        // global hist row
            const int nbase = nt * 128;
            if (tid == 0) spin_ge(&g_cnt[t][2][mt], 32u);
            __syncthreads();

            auto dissue = [&](int ch) {
                if (ch < 16) {
                    const uint32_t sb = sbase + (ch % NSTAGE) * DSTAGEB;
                    const int k0 = ch << 6;
#pragma unroll
                    for (int it = 0; it < 12; it++) {
                        int s = it * 256 + tid;           // 0..3071
                        if (s < 1024) {                    // Ah/Al: 64 rows x 8 c16 each
                            int half = s >> 9;             // 0:Ah 1:Al
                            int q = s & 511; int r = q >> 3, c4 = q & 7;
                            const __half* gp = (half == 0)
                                ? g_histH + (size_t)(rowg0 + r) * HID_ + k0 + c4 * 8
                                : g_histL + (size_t)(rowg0 + r) * HID_ + k0 + c4 * 8;
                            cp16(sb + half * DTA + r * PITCHD + c4 * 16, gp);
                        } else {                           // Bh/Bl: 128 rows x 8 c16 each
                            int q = s - 1024; int half = q >> 10;
                            int q2 = q & 1023; int r = q2 >> 3, c4 = q2 & 7;
                            const __half* gp = (half == 0)
                                ? g_BdH + (size_t)(nbase + r) * HID_ + k0 + c4 * 8
                                : g_BdL + (size_t)(nbase + r) * HID_ + k0 + c4 * 8;
                            cp16(sb + 2 * DTA + half * DTB + r * PITCHD + c4 * 16, gp);
                        }
                    }
                }
                cp_commit();
            };

            float acc[2][4][4];
#pragma unroll
            for (int mf = 0; mf < 2; mf++)
#pragma unroll
                for (int nf = 0; nf < 4; nf++)
#pragma unroll
                    for (int i = 0; i < 4; i++) acc[mf][nf][i] = 0.0f;

            dissue(0); dissue(1);
            for (int ch = 0; ch < 16; ch++) {
                asm volatile("cp.async.wait_group 1;" ::: "memory");
                __syncthreads();
                dissue(ch + 2);
                const uint32_t sb = sbase + (ch % NSTAGE) * DSTAGEB;
#pragma unroll
                for (int kk = 0; kk < 4; kk++) {
                    uint32_t ah[2][4], al[2][4];
#pragma unroll
                    for (int mf = 0; mf < 2; mf++) {
                        uint32_t addr = sb + (uint32_t)(warpm * 32 + mf * 16 + (lane & 15)) * PITCHD
                                      + kk * 32 + (lane >> 4) * 16;
                        ldm_x4(ah[mf], addr);
                        ldm_x4(al[mf], addr + DTA);
                    }
                    uint32_t bh[2][4], bl[2][4];
#pragma unroll
                    for (int nf2 = 0; nf2 < 2; nf2++) {
                        int nrow = warpn * 32 + nf2 * 16 + (lane & 7) + ((lane >> 4) << 3);
                        uint32_t addr = sb + 2 * DTA + (uint32_t)nrow * PITCHD
                                      + kk * 32 + ((lane >> 3) & 1) * 16;
                        ldm_x4(bh[nf2], addr);
                        ldm_x4(bl[nf2], addr + DTB);
                    }
#pragma unroll
                    for (int mf = 0; mf < 2; mf++)
#pragma unroll
                        for (int nf = 0; nf < 4; nf++) {
                            const int nf2 = nf >> 1, h = nf & 1;
                            uint32_t b0h = bh[nf2][h * 2], b1h = bh[nf2][h * 2 + 1];
                            uint32_t b0l = bl[nf2][h * 2], b1l = bl[nf2][h * 2 + 1];
                            mma16816(acc[mf][nf], ah[mf], b0h, b1h);
                            mma16816(acc[mf][nf], ah[mf], b0l, b1l);
                            mma16816(acc[mf][nf], al[mf], b0h, b1h);
                        }
                }
            }
            const int rbase = lane >> 2;
            const int cbase = (lane & 3) * 2;
#pragma unroll
            for (int mf = 0; mf < 2; mf++)
#pragma unroll
                for (int nf = 0; nf < 4; nf++)
#pragma unroll
                    for (int i = 0; i < 4; i++) {
                        int bb = mt * 64 + warpm * 32 + mf * 16 + rbase + (i >> 1) * 8;
                        int n  = nbase + warpn * 32 + nf * 8 + cbase + (i & 1);
                        if (n < INF)
                            out[(size_t)bb * (T_ * INF) + (size_t)t * INF + n] =
                                acc[mf][nf][i] + bd[n];
                    }
            asm volatile("cp.async.wait_group 0;" ::: "memory");
            __syncthreads();
            continue;
        }

        // ================= GATES / FEEDBACK JOB =================
        int typ, z = 0, mbase, nbase, nch, asplit;
        const __half *ap0, *ap1 = nullptr, *bp;
        int as0, as1 = 0, bstr;
        if (jid < 256) {
            typ = 0; z = 1 + (jid & 1);
            int idx = jid >> 1;
            mbase = (idx & 3) * 64; nbase = (idx >> 2) * 128;
            nch = 16; asplit = 16;
            ap0 = Apar + ((z == 2) ? (size_t)A2SZ : 0); as0 = KP2;
            bp  = g_Wh + ((z == 1) ? (size_t)W1SZ : (size_t)(W1SZ + W2SZ)); bstr = KP2;
        } else if (jid < 384) {
            typ = 0; z = 0;
            int idx = jid - 256;
            mbase = (idx & 3) * 64; nbase = (idx >> 2) * 128;
            nch = 10; asplit = 8;
            ap0 = Apar; as0 = KP2;
            ap1 = g_Ax + (size_t)t * (B_ * 256); as1 = 256;
            bp  = g_Wh; bstr = KP1;
        } else {
            typ = 1;
            int idx = jid - 384;
            mbase = (idx & 3) * 64; nbase = (idx >> 2) * 128;
            nch = 8; asplit = 8;
            ap0 = g_histH + (size_t)t * SL; as0 = HID_;
            bp  = g_BdH; bstr = HID_;
        }
        const int mt = mbase >> 6;

        if (tid == 0) {
            if (typ == 1) {
                spin_ge(&g_cnt[t][2][mt], 32u);
            } else if (t > 0) {
                if (z == 0) {
                    spin_ge(&g_cnt[t-1][0][mt], 32u);
                    spin_ge(&g_cnt[t-1][1][mt], 32u);
                    if ((t % 10) >= 5) spin_ge(&g_fbdone[t-1], 8u);
                } else if (z == 1) {
                    spin_ge(&g_cnt[t-1][0][mt], 32u);
                    spin_ge(&g_cnt[t-1][1][mt], 32u);
                    spin_ge(&g_cnt[t-1][2][mt], 32u);
                } else {
                    spin_ge(&g_cnt[t-1][1][mt], 32u);
                    spin_ge(&g_cnt[t-1][2][mt], 32u);
                }
            }
        }
        __syncthreads();

        // loader: A 64x256B (1024 cp16) + B 128x256B (2048 cp16) = 12/thread
        auto issue = [&](int ch) {
            if (ch < nch) {
                const uint32_t sb = sbase + (ch % NSTAGE) * GSTAGEB;
                const int k0 = ch << 7;
#pragma unroll
                for (int it = 0; it < 12; it++) {
                    int s = it * 256 + tid;           // 0..3071
                    if (s < 1024) {                    // A: 64 rows x 16 c16
                        int r = s >> 4, c4 = s & 15;
                        const __half* gp = (ch < asplit)
                            ? ap0 + (size_t)(mbase + r) * as0 + k0 + c4 * 8
                            : ap1 + (size_t)(mbase + r) * as1 + (k0 - (asplit << 7)) + c4 * 8;
                        cp16(sb + r * PITCHG + c4 * 16, gp);
                    } else {                           // B: 128 rows x 16 c16
                        int sB = s - 1024; int r = sB >> 4, c4 = sB & 15;
                        cp16(sb + TILEA + r * PITCHG + c4 * 16,
                             bp + (size_t)(nbase + r) * bstr + k0 + c4 * 8);
                    }
                }
            }
            cp_commit();
        };

        float acc[2][4][4];
#pragma unroll
        for (int mf = 0; mf < 2; mf++)
#pragma unroll
            for (int nf = 0; nf < 4; nf++)
#pragma unroll
                for (int i = 0; i < 4; i++) acc[mf][nf][i] = 0.0f;

        issue(0); issue(1);
        for (int ch = 0; ch < nch; ch++) {
            asm volatile("cp.async.wait_group 1;" ::: "memory");
            __syncthreads();
            issue(ch + 2);
            const uint32_t sb = sbase + (ch % NSTAGE) * GSTAGEB;
#pragma unroll
            for (int kk = 0; kk < 8; kk++) {
                uint32_t ah[2][4];
#pragma unroll
                for (int mf = 0; mf < 2; mf++) {
                    uint32_t addr = sb + (uint32_t)(warpm * 32 + mf * 16 + (lane & 15)) * PITCHG
                                  + kk * 32 + (lane >> 4) * 16;
                    ldm_x4(ah[mf], addr);
                }
                uint32_t bh[2][4];
#pragma unroll
                for (int nf2 = 0; nf2 < 2; nf2++) {
                    int nrow = warpn * 32 + nf2 * 16 + (lane & 7) + ((lane >> 4) << 3);
                    uint32_t addr = sb + TILEA + (uint32_t)nrow * PITCHG
                                  + kk * 32 + ((lane >> 3) & 1) * 16;
                    ldm_x4(bh[nf2], addr);
                }
#pragma unroll
                for (int mf = 0; mf < 2; mf++)
#pragma unroll
                    for (int nf = 0; nf < 4; nf++)
                        mma16816(acc[mf][nf], ah[mf],
                                 bh[nf >> 1][(nf & 1) * 2], bh[nf >> 1][(nf & 1) * 2 + 1]);
            }
        }

        if (typ == 0) {
            const int c     = lane & 3;
            const int pairq = c >> 1;
            const int pos   = c & 1;
            const int rbase = lane >> 2;

            float* cpz = g_c + (size_t)z * SL;
            __half* dst0; __half* dst1 = nullptr;
            if (z == 0)      { dst0 = g_A + (size_t)pn * APAR; }
            else if (z == 1) { dst0 = g_A + (size_t)pn * APAR + 1024;
                               dst1 = g_A + (size_t)pn * APAR + A2SZ; }
            else             { dst0 = g_A + (size_t)pn * APAR + A2SZ + 1024; }

#pragma unroll
            for (int mf = 0; mf < 2; mf++) {
#pragma unroll
                for (int nf = 0; nf < 4; nf++) {
                    float a0 = acc[mf][nf][0], a1 = acc[mf][nf][1];
                    float a2 = acc[mf][nf][2], a3 = acc[mf][nf][3];
                    float p0 = __shfl_xor_sync(0xffffffffu, a0, 1);
                    float p1 = __shfl_xor_sync(0xffffffffu, a1, 1);
                    float p2 = __shfl_xor_sync(0xffffffffu, a2, 1);
                    float p3 = __shfl_xor_sync(0xffffffffu, a3, 1);
                    float iv, fv, gv, ov; int row;
                    if (pos == 0) { iv = a0; fv = a1; gv = p0; ov = p1; row = rbase; }
                    else          { iv = p2; fv = p3; gv = a2; ov = a3; row = rbase + 8; }
                    int n0 = nbase + warpn * 32 + nf * 8 + pairq * 4;
                    float4 bs = *(const float4*)(g_bias + z * NG + n0);
                    iv += bs.x; fv += bs.y; gv += bs.z; ov += bs.w;

                    int b = mbase + warpm * 32 + mf * 16 + row;
                    int j = n0 >> 2;
                    size_t co = (size_t)b * HID_ + j;
                    float cold = __ldcg(cpz + co);
                    float cn = sigf_(fv) * cold + sigf_(iv) * tanhf_(gv);
                    float hn = sigf_(ov) * tanhf_(cn);
                    __stcg(cpz + co, cn);
                    __half hh = __float2half_rn(hn);
                    dst0[(size_t)b * KP2 + j] = hh;
                    if (z == 1) dst1[(size_t)b * KP2 + j] = hh;
                    if (z == 2) {
                        size_t ho = ((size_t)t * B_ + b) * HID_ + j;
                        g_histH[ho] = hh;
                        g_histL[ho] = __float2half_rn(hn - __half2float(hh));
                    }
                }
            }
        } else {
            const int rbase = lane >> 2;
            const int cbase = (lane & 3) * 2;
            __half* xd = g_Ax + (size_t)(t + 1) * (B_ * 256);
#pragma unroll
            for (int mf = 0; mf < 2; mf++)
#pragma unroll
                for (int nf = 0; nf < 4; nf++)
#pragma unroll
                    for (int i = 0; i < 4; i++) {
                        int row = mbase + warpm * 32 + mf * 16 + rbase + (i >> 1) * 8;
                        int n   = nbase + warpn * 32 + nf * 8 + cbase + (i & 1);
                        if (n < INF)
                            xd[(size_t)row * 256 + n] =
                                __float2half_rn(acc[mf][nf][i] + bd[n]);
                    }
        }

        __threadfence();
        asm volatile("cp.async.wait_group 0;" ::: "memory");
        __syncthreads();
        if (tid == 0) {
            if (typ == 0) atomicAdd(&g_cnt[t][z][mt], 1u);
            else          atomicAdd(&g_fbdone[t], 1u);
        }
    }
}

// ---------------- launch ----------------
extern "C" void kernel_launch(void* const* d_in, const int* in_sizes, int n_in,
                              void* d_out, int out_size) {
    (void)in_sizes; (void)n_in; (void)out_size;
    const float* rs   = (const float*)d_in[0];
    const float* Wih1 = (const float*)d_in[1];
    const float* Whh1 = (const float*)d_in[2];
    const float* bih1 = (const float*)d_in[3];
    const float* bhh1 = (const float*)d_in[4];
    const float* Wih2 = (const float*)d_in[5];
    const float* Whh2 = (const float*)d_in[6];
    const float* bih2 = (const float*)d_in[7];
    const float* bhh2 = (const float*)d_in[8];
    const float* Wih3 = (const float*)d_in[9];
    const float* Whh3 = (const float*)d_in[10];
    const float* bih3 = (const float*)d_in[11];
    const float* bhh3 = (const float*)d_in[12];
    const float* Wd   = (const float*)d_in[13];
    const float* bd   = (const float*)d_in[14];
    float* out = (float*)d_out;

    cudaFuncSetAttribute(gates_kernel, cudaFuncAttributeMaxDynamicSharedMemorySize, SMEM_ALL);

    k_zero<<<2048, 256>>>();
    k_setup<<<4096, 256>>>(Wih1, Whh1, Wih2, Whh2, Wih3, Whh3,
                           bih1, bhh1, bih2, bhh2, bih3, bhh3);
    k_setup_bd<<<(256 * HID_ + 255) / 256, 256>>>(Wd);
    stage_x<<<(T_ * B_ * 256) / 256, 256>>>(rs);

    gates_kernel<<<NCTA, 256, SMEM_ALL>>>(bd, out);   // everything in one launch
}